// round 3
// baseline (speedup 1.0000x reference)
#include <cuda_runtime.h>
#include <math_constants.h>
#include <cfloat>
#include <cstddef>

#define F       16
#define CLN     16
#define NBINS   100
#define NEDGE   101      // real edges per feature
#define EPAD    102      // +INF sentinel slot
#define WSIZE   (F * EPAD * CLN)   // 26112 floats = 104448 bytes

// ---------------- scratch (device globals; no allocations) ----------------
__device__ float    g_pmin[256 * F];
__device__ float    g_pmax[256 * F];
__device__ float    g_edges[F * EPAD];
__device__ float    g_lo[F];
__device__ float    g_scale[F];
__device__ unsigned g_counts[F * NBINS];
__device__ float    g_W[WSIZE];

// ---------------- kernel A: per-block min/max over combined ----------------
__global__ void __launch_bounds__(256) kA_minmax(const float* __restrict__ z,
                                                 const float* __restrict__ cl,
                                                 int N) {
    const int t   = threadIdx.x;
    const int tid = blockIdx.x * 256 + t;
    const int total  = N + CLN;
    const int stride = gridDim.x * 256;

    float mn[F], mx[F];
#pragma unroll
    for (int f = 0; f < F; ++f) { mn[f] = FLT_MAX; mx[f] = -FLT_MAX; }

    for (int r = tid; r < total; r += stride) {
        const float4* row = (r < N)
            ? (const float4*)(z  + (size_t)r * F)
            : (const float4*)(cl + (size_t)(r - N) * F);
#pragma unroll
        for (int q = 0; q < 4; ++q) {
            float4 v = row[q];
            mn[4*q+0] = fminf(mn[4*q+0], v.x); mx[4*q+0] = fmaxf(mx[4*q+0], v.x);
            mn[4*q+1] = fminf(mn[4*q+1], v.y); mx[4*q+1] = fmaxf(mx[4*q+1], v.y);
            mn[4*q+2] = fminf(mn[4*q+2], v.z); mx[4*q+2] = fmaxf(mx[4*q+2], v.z);
            mn[4*q+3] = fminf(mn[4*q+3], v.w); mx[4*q+3] = fmaxf(mx[4*q+3], v.w);
        }
    }

    __shared__ float smin[256 * 17];   // pad 17 to dodge bank conflicts
    __shared__ float smax[256 * 17];
#pragma unroll
    for (int f = 0; f < F; ++f) { smin[t*17+f] = mn[f]; smax[t*17+f] = mx[f]; }
    __syncthreads();
    for (int s = 128; s > 0; s >>= 1) {
        if (t < s) {
#pragma unroll
            for (int f = 0; f < F; ++f) {
                smin[t*17+f] = fminf(smin[t*17+f], smin[(t+s)*17+f]);
                smax[t*17+f] = fmaxf(smax[t*17+f], smax[(t+s)*17+f]);
            }
        }
        __syncthreads();
    }
    if (t < F) {
        g_pmin[blockIdx.x * F + t] = smin[t];
        g_pmax[blockIdx.x * F + t] = smax[t];
    }
}

// ---------------- kernel B: finalize lo/hi, build edges, zero counts -------
__global__ void __launch_bounds__(256) kB_edges(int nblk) {
    const int t = threadIdx.x;
    float mn[F], mx[F];
#pragma unroll
    for (int f = 0; f < F; ++f) { mn[f] = FLT_MAX; mx[f] = -FLT_MAX; }
    for (int b = t; b < nblk; b += 256) {
#pragma unroll
        for (int f = 0; f < F; ++f) {
            mn[f] = fminf(mn[f], g_pmin[b * F + f]);
            mx[f] = fmaxf(mx[f], g_pmax[b * F + f]);
        }
    }
    __shared__ float smin[256 * 17];
    __shared__ float smax[256 * 17];
#pragma unroll
    for (int f = 0; f < F; ++f) { smin[t*17+f] = mn[f]; smax[t*17+f] = mx[f]; }
    __syncthreads();
    for (int s = 128; s > 0; s >>= 1) {
        if (t < s) {
#pragma unroll
            for (int f = 0; f < F; ++f) {
                smin[t*17+f] = fminf(smin[t*17+f], smin[(t+s)*17+f]);
                smax[t*17+f] = fmaxf(smax[t*17+f], smax[(t+s)*17+f]);
            }
        }
        __syncthreads();
    }
    __shared__ float lo[F], hi[F];
    if (t < F) { lo[t] = smin[t]; hi[t] = smax[t]; }
    __syncthreads();

    // edges[f][j] = lo + (hi-lo) * t_j ; t_j = j * (1/100) in fp32, t_100 = 1.0 exactly
    for (int idx = t; idx < F * NEDGE; idx += 256) {
        int f = idx / NEDGE, j = idx % NEDGE;
        float tj = (j == NBINS) ? 1.0f : (float)j * 0.01f;
        float d  = __fsub_rn(hi[f], lo[f]);
        g_edges[f * EPAD + j] = __fadd_rn(lo[f], __fmul_rn(d, tj));
    }
    if (t < F) {
        g_edges[t * EPAD + NEDGE] = CUDART_INF_F;  // sentinel
        g_lo[t] = lo[t];
        float d = hi[t] - lo[t];
        g_scale[t] = (d > 0.0f) ? (100.0f / d) : 0.0f;
    }
    for (int i = t; i < F * NBINS; i += 256) g_counts[i] = 0u;
}

// ---------------- kernel C: per-feature histogram (side='right') ----------
__global__ void __launch_bounds__(256) kC_hist(const float* __restrict__ z,
                                               const float* __restrict__ cl,
                                               int N) {
    __shared__ float    se[F * EPAD];
    __shared__ float    slo[F], ssc[F];
    __shared__ unsigned sh[F * NBINS];
    const int t = threadIdx.x;
    for (int i = t; i < F * EPAD;  i += 256) se[i] = g_edges[i];
    if (t < F) { slo[t] = g_lo[t]; ssc[t] = g_scale[t]; }
    for (int i = t; i < F * NBINS; i += 256) sh[i] = 0u;
    __syncthreads();

    const int total  = N + CLN;
    const int stride = gridDim.x * 256;
    for (int r = blockIdx.x * 256 + t; r < total; r += stride) {
        const float4* row = (r < N)
            ? (const float4*)(z  + (size_t)r * F)
            : (const float4*)(cl + (size_t)(r - N) * F);
        float v[F];
#pragma unroll
        for (int q = 0; q < 4; ++q) {
            float4 vv = row[q];
            v[4*q+0]=vv.x; v[4*q+1]=vv.y; v[4*q+2]=vv.z; v[4*q+3]=vv.w;
        }
#pragma unroll
        for (int f = 0; f < F; ++f) {
            float vv = v[f];
            const float* e = se + f * EPAD;
            float cf = fminf(fmaxf((vv - slo[f]) * ssc[f], 0.0f), 100.0f);
            int i = (int)cf;
            // exact searchsorted side='right': first i with e[i] > v
            while (i < NEDGE && e[i] <= vv) ++i;
            while (i > 0 && e[i-1] > vv) --i;
            int bin = i - 1;
            bin = bin < 0 ? 0 : (bin > NBINS-1 ? NBINS-1 : bin);
            atomicAdd(&sh[f * NBINS + bin], 1u);
        }
    }
    __syncthreads();
    for (int i = t; i < F * NBINS; i += 256) {
        unsigned cv = sh[i];
        if (cv) atomicAdd(&g_counts[i], cv);
    }
}

// ---------------- kernel D: cumsum + cluster bins + W table ---------------
__global__ void __launch_bounds__(1024) kD_table(const float* __restrict__ cl, int N) {
    __shared__ float se[F * EPAD];
    __shared__ float slo[F], ssc[F];
    __shared__ float cum[F * NBINS];
    __shared__ int   cb[CLN * F];
    const int t = threadIdx.x;
    for (int i = t; i < F * EPAD; i += 1024) se[i] = g_edges[i];
    if (t < F) { slo[t] = g_lo[t]; ssc[t] = g_scale[t]; }
    __syncthreads();

    if (t < CLN * F) {      // cluster bins, searchsorted side='left' minus 1
        int c = t / F, f = t % F;
        float vv = cl[c * F + f];
        const float* e = se + f * EPAD;
        float cf = fminf(fmaxf((vv - slo[f]) * ssc[f], 0.0f), 101.0f);
        int i = (int)cf;
        while (i < NEDGE && e[i] < vv) ++i;
        while (i > 0 && e[i-1] >= vv) --i;
        cb[c * F + f] = i - 1;
    }
    if (t >= 512 && t < 512 + F) {   // exact float cumsum (integers < 2^24)
        int f = t - 512;
        float run = 0.0f;
        for (int b = 0; b < NBINS; ++b) {
            run += (float)g_counts[f * NBINS + b];
            cum[f * NBINS + b] = run;
        }
    }
    __syncthreads();

    const float divisor = (float)(N + CLN);
    for (int idx = t; idx < WSIZE; idx += 1024) {
        int c   = idx & 15;
        int rem = idx >> 4;
        int r   = rem % EPAD;       // sb + 1 in [0,101]
        int f   = rem / EPAD;
        int sb  = r - 1;
        int cbv = cb[c * F + f];
        int mxb = sb > cbv ? sb : cbv;
        int mnb = sb < cbv ? sb : cbv;
        int hidx = mxb < 0 ? 0 : (mxb > NBINS-1 ? NBINS-1 : mxb);
        float hs  = cum[f * NBINS + hidx];
        float val = (mnb <= 0) ? hs : hs - cum[f * NBINS + (mnb - 1)];
        float w = val / divisor;
        g_W[idx] = w * w;
    }
}

// ---------------- kernel E: main q computation -----------------------------
extern __shared__ float sW[];   // W table, WSIZE floats

__global__ void __launch_bounds__(256) kE_main(const float* __restrict__ z,
                                               float* __restrict__ out,
                                               int N) {
    __shared__ float se[F * EPAD];
    __shared__ float slo[F], ssc[F];
    const int t = threadIdx.x;
    {   // stage W into smem (float4, all L2 hits)
        const float4* src = (const float4*)g_W;
        float4*       dst = (float4*)sW;
        for (int i = t; i < WSIZE / 4; i += 256) dst[i] = src[i];
    }
    for (int i = t; i < F * EPAD; i += 256) se[i] = g_edges[i];
    if (t < F) { slo[t] = g_lo[t]; ssc[t] = g_scale[t]; }
    __syncthreads();

    const int stride = gridDim.x * 256;
    for (int n = blockIdx.x * 256 + t; n < N; n += stride) {
        const float4* zr = (const float4*)(z + (size_t)n * F);
        float4 r0 = zr[0], r1 = zr[1], r2 = zr[2], r3 = zr[3];
        float v[F] = { r0.x, r0.y, r0.z, r0.w,
                       r1.x, r1.y, r1.z, r1.w,
                       r2.x, r2.y, r2.z, r2.w,
                       r3.x, r3.y, r3.z, r3.w };
        float4 a0 = make_float4(0.f,0.f,0.f,0.f);
        float4 a1 = a0, a2 = a0, a3 = a0;
#pragma unroll
        for (int f = 0; f < F; ++f) {
            float vv = v[f];
            const float* e = se + f * EPAD;
            float cf = fminf(fmaxf((vv - slo[f]) * ssc[f], 0.0f), 101.0f);
            int bi = (int)cf;
            // exact searchsorted side='left': first bi with e[bi] >= v
            while (bi < NEDGE && e[bi] < vv) ++bi;
            while (bi > 0 && e[bi-1] >= vv) --bi;
            // bi = sb + 1 in [0,101]
            const float4* w = (const float4*)(sW + (f * EPAD + bi) * CLN);
            float4 w0 = w[0], w1 = w[1], w2 = w[2], w3 = w[3];
            a0.x += w0.x; a0.y += w0.y; a0.z += w0.z; a0.w += w0.w;
            a1.x += w1.x; a1.y += w1.y; a1.z += w1.z; a1.w += w1.w;
            a2.x += w2.x; a2.y += w2.y; a2.z += w2.z; a2.w += w2.w;
            a3.x += w3.x; a3.y += w3.y; a3.z += w3.z; a3.w += w3.w;
        }
        float av[CLN] = { a0.x, a0.y, a0.z, a0.w,
                          a1.x, a1.y, a1.z, a1.w,
                          a2.x, a2.y, a2.z, a2.w,
                          a3.x, a3.y, a3.z, a3.w };
        float q[CLN];
        float s = 0.0f;
#pragma unroll
        for (int c = 0; c < CLN; ++c) {
            float m  = sqrtf(av[c]);
            float qq = 1.0f / (1.0f + m);
            q[c] = qq;
            s += qq;
        }
        float* op = out + (size_t)n * CLN;
        float4 o0 = make_float4(q[0]/s,  q[1]/s,  q[2]/s,  q[3]/s);
        float4 o1 = make_float4(q[4]/s,  q[5]/s,  q[6]/s,  q[7]/s);
        float4 o2 = make_float4(q[8]/s,  q[9]/s,  q[10]/s, q[11]/s);
        float4 o3 = make_float4(q[12]/s, q[13]/s, q[14]/s, q[15]/s);
        ((float4*)op)[0] = o0;
        ((float4*)op)[1] = o1;
        ((float4*)op)[2] = o2;
        ((float4*)op)[3] = o3;
    }
}

// ---------------- launch ----------------------------------------------------
extern "C" void kernel_launch(void* const* d_in, const int* in_sizes, int n_in,
                              void* d_out, int out_size) {
    const float* z  = (const float*)d_in[0];
    const float* cl = (const float*)d_in[1];
    const int N = in_sizes[0] / F;

    cudaFuncSetAttribute(kE_main, cudaFuncAttributeMaxDynamicSharedMemorySize,
                         WSIZE * (int)sizeof(float));

    kA_minmax<<<256, 256>>>(z, cl, N);
    kB_edges <<<1,   256>>>(256);
    kC_hist  <<<256, 256>>>(z, cl, N);
    kD_table <<<1,  1024>>>(cl, N);
    kE_main  <<<304, 256, WSIZE * sizeof(float)>>>(z, (float*)d_out, N);
}

// round 4
// speedup vs baseline: 1.0099x; 1.0099x over previous
#include <cuda_runtime.h>
#include <math_constants.h>
#include <cfloat>
#include <cstddef>

#define F       16
#define CLN     16
#define NBINS   100
#define NEDGE   101      // real edges per feature
#define EPAD    102      // +INF sentinel slot
#define WSIZE   (F * EPAD * CLN)   // 26112 floats = 104448 bytes

// ---------------- scratch (device globals; no allocations) ----------------
__device__ float    g_pmin[256 * F];
__device__ float    g_pmax[256 * F];
__device__ float    g_edges[F * EPAD];
__device__ float    g_lo[F];
__device__ float    g_scale[F];
__device__ unsigned g_counts[F * NBINS];
__device__ float    g_W[WSIZE];

// ---------------- kernel A: per-block min/max over combined ----------------
__global__ void __launch_bounds__(256) kA_minmax(const float* __restrict__ z,
                                                 const float* __restrict__ cl,
                                                 int N) {
    const int t   = threadIdx.x;
    const int tid = blockIdx.x * 256 + t;
    const int total  = N + CLN;
    const int stride = gridDim.x * 256;

    float mn[F], mx[F];
#pragma unroll
    for (int f = 0; f < F; ++f) { mn[f] = FLT_MAX; mx[f] = -FLT_MAX; }

    for (int r = tid; r < total; r += stride) {
        const float4* row = (r < N)
            ? (const float4*)(z  + (size_t)r * F)
            : (const float4*)(cl + (size_t)(r - N) * F);
#pragma unroll
        for (int q = 0; q < 4; ++q) {
            float4 v = row[q];
            mn[4*q+0] = fminf(mn[4*q+0], v.x); mx[4*q+0] = fmaxf(mx[4*q+0], v.x);
            mn[4*q+1] = fminf(mn[4*q+1], v.y); mx[4*q+1] = fmaxf(mx[4*q+1], v.y);
            mn[4*q+2] = fminf(mn[4*q+2], v.z); mx[4*q+2] = fmaxf(mx[4*q+2], v.z);
            mn[4*q+3] = fminf(mn[4*q+3], v.w); mx[4*q+3] = fmaxf(mx[4*q+3], v.w);
        }
    }

    __shared__ float smin[256 * 17];   // pad 17 to dodge bank conflicts
    __shared__ float smax[256 * 17];
#pragma unroll
    for (int f = 0; f < F; ++f) { smin[t*17+f] = mn[f]; smax[t*17+f] = mx[f]; }
    __syncthreads();
    for (int s = 128; s > 0; s >>= 1) {
        if (t < s) {
#pragma unroll
            for (int f = 0; f < F; ++f) {
                smin[t*17+f] = fminf(smin[t*17+f], smin[(t+s)*17+f]);
                smax[t*17+f] = fmaxf(smax[t*17+f], smax[(t+s)*17+f]);
            }
        }
        __syncthreads();
    }
    if (t < F) {
        g_pmin[blockIdx.x * F + t] = smin[t];
        g_pmax[blockIdx.x * F + t] = smax[t];
    }
}

// ---------------- kernel B: finalize lo/hi, build edges, zero counts -------
__global__ void __launch_bounds__(256) kB_edges(int nblk) {
    const int t = threadIdx.x;
    float mn[F], mx[F];
#pragma unroll
    for (int f = 0; f < F; ++f) { mn[f] = FLT_MAX; mx[f] = -FLT_MAX; }
    for (int b = t; b < nblk; b += 256) {
#pragma unroll
        for (int f = 0; f < F; ++f) {
            mn[f] = fminf(mn[f], g_pmin[b * F + f]);
            mx[f] = fmaxf(mx[f], g_pmax[b * F + f]);
        }
    }
    __shared__ float smin[256 * 17];
    __shared__ float smax[256 * 17];
#pragma unroll
    for (int f = 0; f < F; ++f) { smin[t*17+f] = mn[f]; smax[t*17+f] = mx[f]; }
    __syncthreads();
    for (int s = 128; s > 0; s >>= 1) {
        if (t < s) {
#pragma unroll
            for (int f = 0; f < F; ++f) {
                smin[t*17+f] = fminf(smin[t*17+f], smin[(t+s)*17+f]);
                smax[t*17+f] = fmaxf(smax[t*17+f], smax[(t+s)*17+f]);
            }
        }
        __syncthreads();
    }
    __shared__ float lo[F], hi[F];
    if (t < F) { lo[t] = smin[t]; hi[t] = smax[t]; }
    __syncthreads();

    // edges[f][j] = lo + (hi-lo) * t_j ; t_j = j * (1/100) in fp32, t_100 = 1.0 exactly
    for (int idx = t; idx < F * NEDGE; idx += 256) {
        int f = idx / NEDGE, j = idx % NEDGE;
        float tj = (j == NBINS) ? 1.0f : (float)j * 0.01f;
        float d  = __fsub_rn(hi[f], lo[f]);
        g_edges[f * EPAD + j] = __fadd_rn(lo[f], __fmul_rn(d, tj));
    }
    if (t < F) {
        g_edges[t * EPAD + NEDGE] = CUDART_INF_F;  // sentinel
        g_lo[t] = lo[t];
        float d = hi[t] - lo[t];
        g_scale[t] = (d > 0.0f) ? (100.0f / d) : 0.0f;
    }
    for (int i = t; i < F * NBINS; i += 256) g_counts[i] = 0u;
}

// ---------------- kernel C: per-feature histogram (side='right') ----------
__global__ void __launch_bounds__(256) kC_hist(const float* __restrict__ z,
                                               const float* __restrict__ cl,
                                               int N) {
    __shared__ float    se[F * EPAD];
    __shared__ float    slo[F], ssc[F];
    __shared__ unsigned sh[F * NBINS];
    const int t = threadIdx.x;
    for (int i = t; i < F * EPAD;  i += 256) se[i] = g_edges[i];
    if (t < F) { slo[t] = g_lo[t]; ssc[t] = g_scale[t]; }
    for (int i = t; i < F * NBINS; i += 256) sh[i] = 0u;
    __syncthreads();

    const int total  = N + CLN;
    const int stride = gridDim.x * 256;
    for (int r = blockIdx.x * 256 + t; r < total; r += stride) {
        const float4* row = (r < N)
            ? (const float4*)(z  + (size_t)r * F)
            : (const float4*)(cl + (size_t)(r - N) * F);
        float v[F];
#pragma unroll
        for (int q = 0; q < 4; ++q) {
            float4 vv = row[q];
            v[4*q+0]=vv.x; v[4*q+1]=vv.y; v[4*q+2]=vv.z; v[4*q+3]=vv.w;
        }
#pragma unroll
        for (int f = 0; f < F; ++f) {
            float vv = v[f];
            const float* e = se + f * EPAD;
            float cf = fminf(fmaxf((vv - slo[f]) * ssc[f], 0.0f), 100.0f);
            int i = (int)cf;
            // exact searchsorted side='right': first i with e[i] > v
            while (i < NEDGE && e[i] <= vv) ++i;
            while (i > 0 && e[i-1] > vv) --i;
            int bin = i - 1;
            bin = bin < 0 ? 0 : (bin > NBINS-1 ? NBINS-1 : bin);
            atomicAdd(&sh[f * NBINS + bin], 1u);
        }
    }
    __syncthreads();
    for (int i = t; i < F * NBINS; i += 256) {
        unsigned cv = sh[i];
        if (cv) atomicAdd(&g_counts[i], cv);
    }
}

// ---------------- kernel D: cumsum + cluster bins + W table ---------------
__global__ void __launch_bounds__(1024) kD_table(const float* __restrict__ cl, int N) {
    __shared__ float se[F * EPAD];
    __shared__ float slo[F], ssc[F];
    __shared__ float cum[F * NBINS];
    __shared__ int   cb[CLN * F];
    const int t = threadIdx.x;
    for (int i = t; i < F * EPAD; i += 1024) se[i] = g_edges[i];
    if (t < F) { slo[t] = g_lo[t]; ssc[t] = g_scale[t]; }
    __syncthreads();

    if (t < CLN * F) {      // cluster bins, searchsorted side='left' minus 1
        int c = t / F, f = t % F;
        float vv = cl[c * F + f];
        const float* e = se + f * EPAD;
        float cf = fminf(fmaxf((vv - slo[f]) * ssc[f], 0.0f), 101.0f);
        int i = (int)cf;
        while (i < NEDGE && e[i] < vv) ++i;
        while (i > 0 && e[i-1] >= vv) --i;
        cb[c * F + f] = i - 1;
    }
    if (t >= 512 && t < 512 + F) {   // exact float cumsum (integers < 2^24)
        int f = t - 512;
        float run = 0.0f;
        for (int b = 0; b < NBINS; ++b) {
            run += (float)g_counts[f * NBINS + b];
            cum[f * NBINS + b] = run;
        }
    }
    __syncthreads();

    const float divisor = (float)(N + CLN);
    for (int idx = t; idx < WSIZE; idx += 1024) {
        int c   = idx & 15;
        int rem = idx >> 4;
        int r   = rem % EPAD;       // sb + 1 in [0,101]
        int f   = rem / EPAD;
        int sb  = r - 1;
        int cbv = cb[c * F + f];
        int mxb = sb > cbv ? sb : cbv;
        int mnb = sb < cbv ? sb : cbv;
        int hidx = mxb < 0 ? 0 : (mxb > NBINS-1 ? NBINS-1 : mxb);
        float hs  = cum[f * NBINS + hidx];
        float val = (mnb <= 0) ? hs : hs - cum[f * NBINS + (mnb - 1)];
        float w = val / divisor;
        g_W[idx] = w * w;
    }
}

// ---------------- kernel E: main q computation -----------------------------
extern __shared__ float sW[];   // W table, WSIZE floats

__global__ void __launch_bounds__(256) kE_main(const float* __restrict__ z,
                                               float* __restrict__ out,
                                               int N) {
    __shared__ float se[F * EPAD];
    __shared__ float slo[F], ssc[F];
    const int t = threadIdx.x;
    {   // stage W into smem (float4, all L2 hits)
        const float4* src = (const float4*)g_W;
        float4*       dst = (float4*)sW;
        for (int i = t; i < WSIZE / 4; i += 256) dst[i] = src[i];
    }
    for (int i = t; i < F * EPAD; i += 256) se[i] = g_edges[i];
    if (t < F) { slo[t] = g_lo[t]; ssc[t] = g_scale[t]; }
    __syncthreads();

    const int stride = gridDim.x * 256;
    for (int n = blockIdx.x * 256 + t; n < N; n += stride) {
        const float4* zr = (const float4*)(z + (size_t)n * F);
        float4 r0 = zr[0], r1 = zr[1], r2 = zr[2], r3 = zr[3];
        float v[F] = { r0.x, r0.y, r0.z, r0.w,
                       r1.x, r1.y, r1.z, r1.w,
                       r2.x, r2.y, r2.z, r2.w,
                       r3.x, r3.y, r3.z, r3.w };
        float4 a0 = make_float4(0.f,0.f,0.f,0.f);
        float4 a1 = a0, a2 = a0, a3 = a0;
#pragma unroll
        for (int f = 0; f < F; ++f) {
            float vv = v[f];
            const float* e = se + f * EPAD;
            float cf = fminf(fmaxf((vv - slo[f]) * ssc[f], 0.0f), 101.0f);
            int bi = (int)cf;
            // exact searchsorted side='left': first bi with e[bi] >= v
            while (bi < NEDGE && e[bi] < vv) ++bi;
            while (bi > 0 && e[bi-1] >= vv) --bi;
            // bi = sb + 1 in [0,101]
            const float4* w = (const float4*)(sW + (f * EPAD + bi) * CLN);
            float4 w0 = w[0], w1 = w[1], w2 = w[2], w3 = w[3];
            a0.x += w0.x; a0.y += w0.y; a0.z += w0.z; a0.w += w0.w;
            a1.x += w1.x; a1.y += w1.y; a1.z += w1.z; a1.w += w1.w;
            a2.x += w2.x; a2.y += w2.y; a2.z += w2.z; a2.w += w2.w;
            a3.x += w3.x; a3.y += w3.y; a3.z += w3.z; a3.w += w3.w;
        }
        float av[CLN] = { a0.x, a0.y, a0.z, a0.w,
                          a1.x, a1.y, a1.z, a1.w,
                          a2.x, a2.y, a2.z, a2.w,
                          a3.x, a3.y, a3.z, a3.w };
        float q[CLN];
        float s = 0.0f;
#pragma unroll
        for (int c = 0; c < CLN; ++c) {
            float m  = sqrtf(av[c]);
            float qq = 1.0f / (1.0f + m);
            q[c] = qq;
            s += qq;
        }
        float* op = out + (size_t)n * CLN;
        float4 o0 = make_float4(q[0]/s,  q[1]/s,  q[2]/s,  q[3]/s);
        float4 o1 = make_float4(q[4]/s,  q[5]/s,  q[6]/s,  q[7]/s);
        float4 o2 = make_float4(q[8]/s,  q[9]/s,  q[10]/s, q[11]/s);
        float4 o3 = make_float4(q[12]/s, q[13]/s, q[14]/s, q[15]/s);
        ((float4*)op)[0] = o0;
        ((float4*)op)[1] = o1;
        ((float4*)op)[2] = o2;
        ((float4*)op)[3] = o3;
    }
}

// ---------------- launch ----------------------------------------------------
extern "C" void kernel_launch(void* const* d_in, const int* in_sizes, int n_in,
                              void* d_out, int out_size) {
    const float* z  = (const float*)d_in[0];
    const float* cl = (const float*)d_in[1];
    const int N = in_sizes[0] / F;

    cudaFuncSetAttribute(kE_main, cudaFuncAttributeMaxDynamicSharedMemorySize,
                         WSIZE * (int)sizeof(float));

    kA_minmax<<<256, 256>>>(z, cl, N);
    kB_edges <<<1,   256>>>(256);
    kC_hist  <<<256, 256>>>(z, cl, N);
    kD_table <<<1,  1024>>>(cl, N);
    kE_main  <<<304, 256, WSIZE * sizeof(float)>>>(z, (float*)d_out, N);
}